// round 4
// baseline (speedup 1.0000x reference)
#include <cuda_runtime.h>
#include <cstdint>
#include <cstddef>

#define BN_ 4
#define TN_ 2048
#define SN_ 2048
#define EN_ 512
#define HN_ 8
#define DH_ 64
#define MPROJ (BN_ * TN_)
#define OUT0_ELEMS ((size_t)BN_ * TN_ * EN_)
#define P_ELEMS    ((size_t)BN_ * HN_ * TN_ * SN_)

__device__ float g_Q[(size_t)MPROJ * EN_];
__device__ float g_K[(size_t)MPROJ * EN_];
__device__ float g_V[(size_t)MPROJ * EN_];
__device__ float g_CTX[(size_t)MPROJ * EN_];
__device__ float g_INVL[(size_t)BN_ * HN_ * TN_];
__device__ float g_P[P_ELEMS];

__device__ __forceinline__ uint32_t f2tf32(float x) {
    uint32_t r;
    asm("cvt.rna.tf32.f32 %0, %1;" : "=r"(r) : "f"(x));
    return r;
}

__device__ __forceinline__ void mma_tf32(
    float& d0, float& d1, float& d2, float& d3,
    uint32_t a0, uint32_t a1, uint32_t a2, uint32_t a3,
    uint32_t b0, uint32_t b1)
{
    asm volatile(
        "mma.sync.aligned.m16n8k8.row.col.f32.tf32.tf32.f32 "
        "{%0,%1,%2,%3}, {%4,%5,%6,%7}, {%8,%9}, {%0,%1,%2,%3};"
        : "+f"(d0), "+f"(d1), "+f"(d2), "+f"(d3)
        : "r"(a0), "r"(a1), "r"(a2), "r"(a3), "r"(b0), "r"(b1));
}

// ---------------------------------------------------------------------------
// Kernel A: fused scores + mask + exp + row-sum.
// One block owns 128 t-rows of one (b,h); loops over all 16 s-tiles of 128.
// Writes E = exp(masked score) to P (unnormalized) and invl = 1/rowsum.
// Qs/Ks: [row][k] stride 68 (bank-conflict-free for the 4g+t access).
// ---------------------------------------------------------------------------
__global__ __launch_bounds__(256, 2) void scores_exp_kernel(
    const float* __restrict__ Q, const float* __restrict__ Kp,
    const unsigned char* __restrict__ attn_mask,
    const unsigned char* __restrict__ kpm,
    float* __restrict__ P, float* __restrict__ invl)
{
    extern __shared__ uint32_t smem_u[];
    uint32_t* Qs = smem_u;               // 128*68
    uint32_t* Ks = smem_u + 128 * 68;    // 128*68
    __shared__ float ssum[4][128];

    int bh = blockIdx.y;
    int b = bh >> 3;
    int h = bh & 7;
    int t0 = blockIdx.x * 128;
    int tid = threadIdx.x;
    int warp = tid >> 5, lane = tid & 31;
    int g = lane >> 2, t = lane & 3;
    int wm = (warp >> 2) * 64;   // 0 or 64
    int wn = (warp & 3) * 32;    // 0..96

    const float* Qb = Q + (size_t)b * TN_ * EN_ + (size_t)h * DH_;
    const float* Kb = Kp + (size_t)b * SN_ * EN_ + (size_t)h * DH_;
    float* Pb = P + (size_t)bh * TN_ * SN_;

    // Load Q tile once: 128 rows x 64 k
#pragma unroll
    for (int i = 0; i < 4; i++) {
        int f = tid + i * 256;
        int r = f >> 3;          // 0..127
        int c = (f & 7) * 8;     // 0..56
        float4 q0 = *(const float4*)&Qb[(size_t)(t0 + r) * EN_ + c];
        float4 q1 = *(const float4*)&Qb[(size_t)(t0 + r) * EN_ + c + 4];
        Qs[r * 68 + c + 0] = f2tf32(q0.x); Qs[r * 68 + c + 1] = f2tf32(q0.y);
        Qs[r * 68 + c + 2] = f2tf32(q0.z); Qs[r * 68 + c + 3] = f2tf32(q0.w);
        Qs[r * 68 + c + 4] = f2tf32(q1.x); Qs[r * 68 + c + 5] = f2tf32(q1.y);
        Qs[r * 68 + c + 6] = f2tf32(q1.z); Qs[r * 68 + c + 7] = f2tf32(q1.w);
    }

    float partial[4][2] = {};   // row sums: [m-tile][half]

    for (int sIt = 0; sIt < SN_ / 128; sIt++) {
        int s0 = sIt * 128;
        __syncthreads();   // previous mma done reading Ks
#pragma unroll
        for (int i = 0; i < 4; i++) {
            int f = tid + i * 256;
            int r = f >> 3;
            int c = (f & 7) * 8;
            float4 k0 = *(const float4*)&Kb[(size_t)(s0 + r) * EN_ + c];
            float4 k1 = *(const float4*)&Kb[(size_t)(s0 + r) * EN_ + c + 4];
            Ks[r * 68 + c + 0] = f2tf32(k0.x); Ks[r * 68 + c + 1] = f2tf32(k0.y);
            Ks[r * 68 + c + 2] = f2tf32(k0.z); Ks[r * 68 + c + 3] = f2tf32(k0.w);
            Ks[r * 68 + c + 4] = f2tf32(k1.x); Ks[r * 68 + c + 5] = f2tf32(k1.y);
            Ks[r * 68 + c + 6] = f2tf32(k1.z); Ks[r * 68 + c + 7] = f2tf32(k1.w);
        }
        __syncthreads();   // Ks (and Qs on iter 0) visible

        float acc[4][4][4] = {};
#pragma unroll
        for (int kk = 0; kk < 64; kk += 8) {
            uint32_t a[4][4];
#pragma unroll
            for (int i = 0; i < 4; i++) {
                int base = (wm + 16 * i + g) * 68 + kk + t;
                a[i][0] = Qs[base];
                a[i][1] = Qs[base + 8 * 68];
                a[i][2] = Qs[base + 4];
                a[i][3] = Qs[base + 8 * 68 + 4];
            }
            uint32_t bf[4][2];
#pragma unroll
            for (int j = 0; j < 4; j++) {
                int base = (wn + 8 * j + g) * 68 + kk + t;
                bf[j][0] = Ks[base];
                bf[j][1] = Ks[base + 4];
            }
#pragma unroll
            for (int i = 0; i < 4; i++)
#pragma unroll
                for (int j = 0; j < 4; j++)
                    mma_tf32(acc[i][j][0], acc[i][j][1], acc[i][j][2], acc[i][j][3],
                             a[i][0], a[i][1], a[i][2], a[i][3], bf[j][0], bf[j][1]);
        }

        // Epilogue: mask + exp + write E + accumulate row sums
#pragma unroll
        for (int j = 0; j < 4; j++) {
            int cl = wn + 8 * j + 2 * t;
            int s_g = s0 + cl;
            uchar2 kp2 = *(const uchar2*)&kpm[(size_t)b * SN_ + s_g];
#pragma unroll
            for (int i = 0; i < 4; i++) {
                int tg0 = t0 + wm + 16 * i + g;
                int tg1 = tg0 + 8;
                uchar2 am0 = *(const uchar2*)&attn_mask[(size_t)tg0 * SN_ + s_g];
                uchar2 am1 = *(const uchar2*)&attn_mask[(size_t)tg1 * SN_ + s_g];
                float e00 = (am0.x | kp2.x) ? 0.f : __expf(acc[i][j][0]);
                float e01 = (am0.y | kp2.y) ? 0.f : __expf(acc[i][j][1]);
                float e10 = (am1.x | kp2.x) ? 0.f : __expf(acc[i][j][2]);
                float e11 = (am1.y | kp2.y) ? 0.f : __expf(acc[i][j][3]);
                *(float2*)&Pb[(size_t)tg0 * SN_ + s_g] = make_float2(e00, e01);
                *(float2*)&Pb[(size_t)tg1 * SN_ + s_g] = make_float2(e10, e11);
                partial[i][0] += e00 + e01;
                partial[i][1] += e10 + e11;
            }
        }
    }

    // Reduce row sums: quad (over t) via shfl, then across 4 col-group warps.
#pragma unroll
    for (int i = 0; i < 4; i++)
#pragma unroll
        for (int hh = 0; hh < 2; hh++) {
            float v = partial[i][hh];
            v += __shfl_xor_sync(0xFFFFFFFFu, v, 1);
            v += __shfl_xor_sync(0xFFFFFFFFu, v, 2);
            partial[i][hh] = v;
        }
    if (t == 0) {
#pragma unroll
        for (int i = 0; i < 4; i++)
#pragma unroll
            for (int hh = 0; hh < 2; hh++) {
                int rl = wm + 16 * i + 8 * hh + g;
                ssum[warp & 3][rl] = partial[i][hh];
            }
    }
    __syncthreads();
    if (tid < 128) {
        float l = ssum[0][tid] + ssum[1][tid] + ssum[2][tid] + ssum[3][tid];
        invl[(size_t)bh * TN_ + t0 + tid] = 1.0f / l;
    }
}

// ---------------------------------------------------------------------------
// Kernel B: fused PV + P normalization write-back.
// Ctx[128 t x 64 d] = (E[128,2048] @ V_h[2048,64]) * invl; P <- E * invl.
// ---------------------------------------------------------------------------
__global__ __launch_bounds__(256) void pv_norm_kernel(
    float* __restrict__ P, const float* __restrict__ V,
    const float* __restrict__ invl, float* __restrict__ Ctx)
{
    __shared__ uint32_t Ps[128 * 36];
    __shared__ uint32_t Vs[32 * 72];
    __shared__ float sinv[128];

    int bh = blockIdx.y;
    int b = bh >> 3;
    int h = bh & 7;
    int t0 = blockIdx.x * 128;
    int tid = threadIdx.x;
    int warp = tid >> 5, lane = tid & 31;
    int g = lane >> 2, t = lane & 3;
    int wm = (warp >> 1) * 32;
    int wn = (warp & 1) * 32;

    float* Pb = P + ((size_t)bh * TN_ + t0) * SN_;
    const float* Vb = V + (size_t)b * SN_ * EN_ + (size_t)h * DH_;

    if (tid < 128) sinv[tid] = invl[(size_t)bh * TN_ + t0 + tid];
    __syncthreads();

    float acc[2][4][4] = {};

    for (int k0 = 0; k0 < SN_; k0 += 32) {
#pragma unroll
        for (int i = 0; i < 4; i++) {
            int f = tid + i * 256;
            int r = f >> 3;          // 0..127
            int c = (f & 7) * 4;     // 0..28
            float4 v = *(const float4*)&Pb[(size_t)r * SN_ + k0 + c];
            Ps[r * 36 + c + 0] = f2tf32(v.x); Ps[r * 36 + c + 1] = f2tf32(v.y);
            Ps[r * 36 + c + 2] = f2tf32(v.z); Ps[r * 36 + c + 3] = f2tf32(v.w);
            float iv = sinv[r];
            *(float4*)&Pb[(size_t)r * SN_ + k0 + c] =
                make_float4(v.x * iv, v.y * iv, v.z * iv, v.w * iv);
        }
#pragma unroll
        for (int i = 0; i < 2; i++) {
            int f = tid + i * 256;
            int r = f >> 4;          // 0..31
            int c = (f & 15) * 4;    // 0..60
            float4 v = *(const float4*)&Vb[(size_t)(k0 + r) * EN_ + c];
            Vs[r * 72 + c + 0] = f2tf32(v.x); Vs[r * 72 + c + 1] = f2tf32(v.y);
            Vs[r * 72 + c + 2] = f2tf32(v.z); Vs[r * 72 + c + 3] = f2tf32(v.w);
        }
        __syncthreads();

#pragma unroll
        for (int kk = 0; kk < 32; kk += 8) {
            uint32_t a[2][4];
#pragma unroll
            for (int i = 0; i < 2; i++) {
                int base = (wm + 16 * i + g) * 36 + kk + t;
                a[i][0] = Ps[base];
                a[i][1] = Ps[base + 8 * 36];
                a[i][2] = Ps[base + 4];
                a[i][3] = Ps[base + 8 * 36 + 4];
            }
            uint32_t bf[4][2];
#pragma unroll
            for (int j = 0; j < 4; j++) {
                int col = wn + 8 * j + g;
                bf[j][0] = Vs[(kk + t) * 72 + col];
                bf[j][1] = Vs[(kk + t + 4) * 72 + col];
            }
#pragma unroll
            for (int i = 0; i < 2; i++)
#pragma unroll
                for (int j = 0; j < 4; j++)
                    mma_tf32(acc[i][j][0], acc[i][j][1], acc[i][j][2], acc[i][j][3],
                             a[i][0], a[i][1], a[i][2], a[i][3], bf[j][0], bf[j][1]);
        }
        __syncthreads();
    }

#pragma unroll
    for (int i = 0; i < 2; i++) {
        int rl0 = wm + 16 * i + g;
        int rl1 = rl0 + 8;
        float iv0 = sinv[rl0], iv1 = sinv[rl1];
        int r0 = t0 + rl0, r1 = t0 + rl1;
#pragma unroll
        for (int j = 0; j < 4; j++) {
            int d = wn + 8 * j + 2 * t;
            size_t o0 = (size_t)b * TN_ * EN_ + (size_t)r0 * EN_ + (size_t)h * DH_ + d;
            size_t o1 = (size_t)b * TN_ * EN_ + (size_t)r1 * EN_ + (size_t)h * DH_ + d;
            *(float2*)&Ctx[o0] = make_float2(acc[i][j][0] * iv0, acc[i][j][1] * iv0);
            *(float2*)&Ctx[o1] = make_float2(acc[i][j][2] * iv1, acc[i][j][3] * iv1);
        }
    }
}

// ---------------------------------------------------------------------------
// Projection GEMM (tf32 mma): C[M,N] = (A @ W + b) * scale
// ---------------------------------------------------------------------------
__global__ __launch_bounds__(256) void gemm_bias_kernel(
    const float* __restrict__ A, const float* __restrict__ W,
    const float* __restrict__ bias, float* __restrict__ C,
    int M, int N, int K, float scale)
{
    __shared__ uint32_t As[128 * 20];
    __shared__ uint32_t Ws[16 * 136];

    int tid = threadIdx.x;
    int warp = tid >> 5, lane = tid & 31;
    int g = lane >> 2, t = lane & 3;
    int wm = (warp >> 2) * 64;
    int wn = (warp & 3) * 32;
    int bm = blockIdx.y * 128, bn = blockIdx.x * 128;

    float acc[4][4][4] = {};

    for (int k0 = 0; k0 < K; k0 += 16) {
#pragma unroll
        for (int i = 0; i < 2; i++) {
            int f = tid + i * 256;
            int r = f >> 2;
            int c = (f & 3) * 4;
            float4 v = *(const float4*)&A[(size_t)(bm + r) * K + k0 + c];
            As[r * 20 + c + 0] = f2tf32(v.x); As[r * 20 + c + 1] = f2tf32(v.y);
            As[r * 20 + c + 2] = f2tf32(v.z); As[r * 20 + c + 3] = f2tf32(v.w);
        }
#pragma unroll
        for (int i = 0; i < 2; i++) {
            int f = tid + i * 256;
            int r = f >> 5;
            int c = (f & 31) * 4;
            float4 v = *(const float4*)&W[(size_t)(k0 + r) * N + bn + c];
            Ws[r * 136 + c + 0] = f2tf32(v.x); Ws[r * 136 + c + 1] = f2tf32(v.y);
            Ws[r * 136 + c + 2] = f2tf32(v.z); Ws[r * 136 + c + 3] = f2tf32(v.w);
        }
        __syncthreads();

#pragma unroll
        for (int kk = 0; kk < 16; kk += 8) {
            uint32_t a[4][4];
#pragma unroll
            for (int i = 0; i < 4; i++) {
                int base = (wm + 16 * i + g) * 20 + kk + t;
                a[i][0] = As[base];
                a[i][1] = As[base + 8 * 20];
                a[i][2] = As[base + 4];
                a[i][3] = As[base + 8 * 20 + 4];
            }
            uint32_t bf[4][2];
#pragma unroll
            for (int j = 0; j < 4; j++) {
                int col = wn + 8 * j + g;
                bf[j][0] = Ws[(kk + t) * 136 + col];
                bf[j][1] = Ws[(kk + t + 4) * 136 + col];
            }
#pragma unroll
            for (int i = 0; i < 4; i++)
#pragma unroll
                for (int j = 0; j < 4; j++)
                    mma_tf32(acc[i][j][0], acc[i][j][1], acc[i][j][2], acc[i][j][3],
                             a[i][0], a[i][1], a[i][2], a[i][3], bf[j][0], bf[j][1]);
        }
        __syncthreads();
    }

#pragma unroll
    for (int i = 0; i < 4; i++) {
        int r0 = bm + wm + 16 * i + g;
        int r1 = r0 + 8;
#pragma unroll
        for (int j = 0; j < 4; j++) {
            int c = bn + wn + 8 * j + 2 * t;
            float b0 = bias[c], b1 = bias[c + 1];
            *(float2*)&C[(size_t)r0 * N + c] =
                make_float2((acc[i][j][0] + b0) * scale, (acc[i][j][1] + b1) * scale);
            *(float2*)&C[(size_t)r1 * N + c] =
                make_float2((acc[i][j][2] + b0) * scale, (acc[i][j][3] + b1) * scale);
        }
    }
}

// ---------------------------------------------------------------------------
extern "C" void kernel_launch(void* const* d_in, const int* in_sizes, int n_in,
                              void* d_out, int out_size)
{
    const float* query = (const float*)d_in[0];
    const float* key   = (const float*)d_in[1];
    const float* value = (const float*)d_in[2];
    const unsigned char* kpm       = (const unsigned char*)d_in[3];
    const unsigned char* attn_mask = (const unsigned char*)d_in[4];
    const float* Wq = (const float*)d_in[5];
    const float* bq = (const float*)d_in[6];
    const float* Wk = (const float*)d_in[7];
    const float* bk = (const float*)d_in[8];
    const float* Wv = (const float*)d_in[9];
    const float* bv = (const float*)d_in[10];
    const float* Wo = (const float*)d_in[11];
    const float* bo = (const float*)d_in[12];

    float* out = (float*)d_out;

    float *Qp, *Kp, *Vp, *Ctx, *Pfb, *Inv;
    cudaGetSymbolAddress((void**)&Qp,  g_Q);
    cudaGetSymbolAddress((void**)&Kp,  g_K);
    cudaGetSymbolAddress((void**)&Vp,  g_V);
    cudaGetSymbolAddress((void**)&Ctx, g_CTX);
    cudaGetSymbolAddress((void**)&Pfb, g_P);
    cudaGetSymbolAddress((void**)&Inv, g_INVL);

    float* P = ((size_t)out_size >= OUT0_ELEMS + P_ELEMS) ? (out + OUT0_ELEMS) : Pfb;

    dim3 blk(256);
    dim3 gProj(EN_ / 128, MPROJ / 128);   // (4, 64)

    const float scaling = 0.125f;

    gemm_bias_kernel<<<gProj, blk>>>(query, Wq, bq, Qp, MPROJ, EN_, EN_, scaling);
    gemm_bias_kernel<<<gProj, blk>>>(key,   Wk, bk, Kp, MPROJ, EN_, EN_, 1.0f);
    gemm_bias_kernel<<<gProj, blk>>>(value, Wv, bv, Vp, MPROJ, EN_, EN_, 1.0f);

    static int smem_set = 0;
    int smemA = 2 * 128 * 68 * 4;   // ~69.6 KB
    if (!smem_set) {
        cudaFuncSetAttribute(scores_exp_kernel, cudaFuncAttributeMaxDynamicSharedMemorySize, smemA);
        smem_set = 1;
    }
    dim3 gA(TN_ / 128, BN_ * HN_);   // (16, 32)
    scores_exp_kernel<<<gA, blk, smemA>>>(Qp, Kp, attn_mask, kpm, P, Inv);

    dim3 gB(TN_ / 128, BN_ * HN_);   // (16, 32)
    pv_norm_kernel<<<gB, blk>>>(P, Vp, Inv, Ctx);

    gemm_bias_kernel<<<gProj, blk>>>(Ctx, Wo, bo, out, MPROJ, EN_, EN_, 1.0f);
}